// round 10
// baseline (speedup 1.0000x reference)
#include <cuda_runtime.h>
#include <cuda_bf16.h>
#include <math.h>

#define N_NODES 100000
#define N_EDGES 640000
#define IN_FEATS 256
#define HEADS 4
#define OUT_FEATS 32
#define HD (HEADS * OUT_FEATS)   // 128
#define NEG_SLOPE 0.2f

#define HIST_BLOCKS  ((N_EDGES / 4 + 255) / 256)     // 625
#define GEMM_BLOCKS  ((N_NODES + 127) / 128)         // 782
#define SCAN_BLOCKS  98                              // ceil(100000/1024)
#define SCAT_BLOCKS  ((N_EDGES + 255) / 256)         // 2500
#define WPREP_BLOCKS 32                              // blocks doing W round/permute

// GEMM smem geometry (floats)
#define AS_STRIDE 36
#define BS_STRIDE 132
#define AS_STAGE (128 * AS_STRIDE)
#define BS_STAGE (32 * BS_STRIDE)
#define GEMM_SMEM_BYTES ((2 * AS_STAGE + 2 * BS_STAGE) * 4)   // 70656 B

// ---------------- scratch (no allocs allowed) ----------------
__device__ float    g_ft[(size_t)N_NODES * HD];
__device__ float    g_el[N_NODES * HEADS];
__device__ float    g_er[N_NODES * HEADS];
__device__ float    g_e [(size_t)N_EDGES * HEADS];   // big-degree nodes only
__device__ float    g_wt[IN_FEATS * HD];             // tf32-rounded, permuted W
__device__ int      g_pool[N_NODES + 260];           // counts+scan states+flags
__device__ int      g_offsets[N_NODES + 1];
__device__ int      g_cursor[N_NODES];
__device__ unsigned long long g_csr[N_EDGES];        // (src<<32)|edge_id

#define G_COUNTS (g_pool)
#define G_STATE  ((unsigned long long*)(g_pool + N_NODES))
#define F_HIST   (g_pool + N_NODES + 256)
#define F_SCAN   (g_pool + N_NODES + 257)
#define F_WPREP  (g_pool + N_NODES + 258)

// ---------------- helpers ----------------
__device__ __forceinline__ unsigned tf32_bits(float x) {
    unsigned u;
    asm("cvt.rna.tf32.f32 %0, %1;" : "=r"(u) : "f"(x));
    return u;
}
__device__ __forceinline__ float to_tf32(float x) {
    return __uint_as_float(tf32_bits(x));
}
__device__ __forceinline__ void cp_async16(unsigned smem, const void* gmem,
                                           int src_bytes) {
    asm volatile("cp.async.cg.shared.global [%0], [%1], 16, %2;"
                 :: "r"(smem), "l"(gmem), "r"(src_bytes));
}
__device__ __forceinline__ void cp_commit() {
    asm volatile("cp.async.commit_group;");
}
__device__ __forceinline__ void mma_tf32(float* d, const unsigned* a,
                                         unsigned b0, unsigned b1) {
    asm volatile(
        "mma.sync.aligned.m16n8k8.row.col.f32.tf32.tf32.f32 "
        "{%0,%1,%2,%3}, {%4,%5,%6,%7}, {%8,%9}, {%0,%1,%2,%3};"
        : "+f"(d[0]), "+f"(d[1]), "+f"(d[2]), "+f"(d[3])
        : "r"(a[0]), "r"(a[1]), "r"(a[2]), "r"(a[3]), "r"(b0), "r"(b1));
}
// thread-0 spin (acquire) until *flag >= target
__device__ __forceinline__ void wait_flag(int* flag, int target) {
    if (threadIdx.x == 0) {
        while (atomicAdd(flag, 0) < target) __nanosleep(128);
    }
    __syncthreads();
    __threadfence();
}
// release: count this block into *flag
__device__ __forceinline__ void signal_flag(int* flag) {
    __syncthreads();
    __threadfence();
    if (threadIdx.x == 0) atomicAdd(flag, 1);
}

// ---------------- role: histogram + W prep ----------------------------------
__device__ void hist_role(int bx, const int* __restrict__ dst,
                          const float* __restrict__ W) {
    int i = bx * 256 + threadIdx.x;
    if (i < (IN_FEATS * HD) / 4) {
        float4 v = ((const float4*)W)[i];
        int k = (i * 4) / HD;
        int n = (i * 4) % HD;
        float vv[4] = {to_tf32(v.x), to_tf32(v.y), to_tf32(v.z), to_tf32(v.w)};
#pragma unroll
        for (int q = 0; q < 4; q++) {
            int nn = n + q;
            int p = (nn & 7) * 16 + ((nn >> 6) & 1) * 8 + ((nn >> 3) & 7);
            g_wt[k * HD + p] = vv[q];
        }
    }
    if (i < N_EDGES / 4) {
        int4 d = ((const int4*)dst)[i];
        atomicAdd(&G_COUNTS[d.x], 1);
        atomicAdd(&G_COUNTS[d.y], 1);
        atomicAdd(&G_COUNTS[d.z], 1);
        atomicAdd(&G_COUNTS[d.w], 1);
    }
    if (bx < WPREP_BLOCKS) signal_flag(F_WPREP);
    signal_flag(F_HIST);
}

// ---------------- role: scan (decoupled lookback) ----------------------------
__device__ void scan_role(int b, int* smi) {
    wait_flag(F_HIST, HIST_BLOCKS);
    const int t = threadIdx.x;
    const int lane = t & 31, w = t >> 5;
    const int base = b * 1024 + t * 4;

    int v0 = 0, v1 = 0, v2 = 0, v3 = 0;
    if (base + 3 < N_NODES) {
        int4 q = *(const int4*)(G_COUNTS + base);
        v0 = q.x; v1 = q.y; v2 = q.z; v3 = q.w;
    } else {
        if (base + 0 < N_NODES) v0 = G_COUNTS[base + 0];
        if (base + 1 < N_NODES) v1 = G_COUNTS[base + 1];
        if (base + 2 < N_NODES) v2 = G_COUNTS[base + 2];
        if (base + 3 < N_NODES) v3 = G_COUNTS[base + 3];
    }
    int tsum = v0 + v1 + v2 + v3;
    int x = tsum;
#pragma unroll
    for (int o = 1; o < 32; o <<= 1) {
        int u = __shfl_up_sync(0xffffffffu, x, o);
        if (lane >= o) x += u;
    }
    if (lane == 31) smi[w] = x;
    __syncthreads();
    if (t < 8) {
        int acc = 0;
        for (int j = 0; j <= t; j++) acc += smi[j];
        smi[t + 16] = acc;
    }
    __syncthreads();
    int warp_off = (w > 0) ? smi[16 + w - 1] : 0;
    int total = smi[16 + 7];

    if (t == 0) {
        unsigned long long* st = G_STATE;
        int excl = 0;
        if (b == 0) {
            __threadfence();
            atomicExch(&st[0], (2ULL << 32) | (unsigned)total);
        } else {
            __threadfence();
            atomicExch(&st[b], (1ULL << 32) | (unsigned)total);
            for (int j = b - 1; j >= 0;) {
                unsigned long long sv;
                do { sv = atomicAdd(&st[j], 0ULL); } while ((sv >> 32) == 0ULL);
                excl += (int)(sv & 0xffffffffULL);
                if ((sv >> 32) == 2ULL) break;
                j--;
            }
            __threadfence();
            atomicExch(&st[b], (2ULL << 32) | (unsigned)(excl + total));
        }
        smi[8] = excl;
    }
    __syncthreads();
    int pre = smi[8] + warp_off + (x - tsum);

    int o0 = pre, o1 = pre + v0, o2 = pre + v0 + v1, o3 = pre + v0 + v1 + v2;
    if (base + 3 < N_NODES) {
        *(int4*)(g_offsets + base) = make_int4(o0, o1, o2, o3);
        *(int4*)(g_cursor  + base) = make_int4(o0, o1, o2, o3);
    } else {
        if (base + 0 < N_NODES) { g_offsets[base+0] = o0; g_cursor[base+0] = o0; }
        if (base + 1 < N_NODES) { g_offsets[base+1] = o1; g_cursor[base+1] = o1; }
        if (base + 2 < N_NODES) { g_offsets[base+2] = o2; g_cursor[base+2] = o2; }
        if (base + 3 < N_NODES) { g_offsets[base+3] = o3; g_cursor[base+3] = o3; }
    }
    if (b == 0 && t == 0) g_offsets[N_NODES] = N_EDGES;
    signal_flag(F_SCAN);
}

// ---------------- role: scatter ----------------------------------------------
__device__ void scatter_role(int bx, const int* __restrict__ src,
                             const int* __restrict__ dst) {
    wait_flag(F_SCAN, SCAN_BLOCKS);
    int e = bx * 256 + threadIdx.x;
    if (e >= N_EDGES) return;
    int pos = atomicAdd(&g_cursor[dst[e]], 1);
    g_csr[pos] = ((unsigned long long)(unsigned)src[e] << 32) | (unsigned)e;
}

// ---------------- role: GEMM (TF32 MMA, cp.async 2-stage) + el/er ------------
__device__ void gemm_role(int bidx, const float* __restrict__ A,
                          const float* __restrict__ attn_l,
                          const float* __restrict__ attn_r,
                          float* __restrict__ C, float* sm) {
    wait_flag(F_WPREP, WPREP_BLOCKS);
    const float* B = g_wt;
    const unsigned sm_u32 = (unsigned)__cvta_generic_to_shared(sm);
    const int tid  = threadIdx.x;
    const int warp = tid >> 5, lane = tid & 31;
    const int wm = warp >> 1, wn = warp & 1;
    const int g = lane >> 2, c = lane & 3;
    const int blockM = bidx * 128;

    float acc[2][8][4];
#pragma unroll
    for (int i = 0; i < 2; i++)
#pragma unroll
        for (int j = 0; j < 8; j++)
#pragma unroll
            for (int r = 0; r < 4; r++) acc[i][j][r] = 0.0f;

    auto load_stage = [&](int stage, int k0) {
        unsigned as_base = sm_u32 + (unsigned)(stage * AS_STAGE) * 4u;
        unsigned bs_base = sm_u32 + (unsigned)((2 * AS_STAGE) + stage * BS_STAGE) * 4u;
#pragma unroll
        for (int it = 0; it < 4; it++) {
            int f   = tid + it * 256;
            int row = f >> 3;
            int seg = f & 7;
            int grow = blockM + row;
            int sz = (grow < N_NODES) ? 16 : 0;
            cp_async16(as_base + (unsigned)(row * AS_STRIDE + seg * 4) * 4u,
                       A + (size_t)grow * IN_FEATS + k0 + seg * 4, sz);
        }
#pragma unroll
        for (int it = 0; it < 4; it++) {
            int f  = tid + it * 256;
            int kr = f >> 5;
            int cs = (f & 31) * 4;
            cp_async16(bs_base + (unsigned)(kr * BS_STRIDE + cs) * 4u,
                       B + (size_t)(k0 + kr) * HD + cs, 16);
        }
    };

    load_stage(0, 0);
    cp_commit();

    for (int i = 0; i < 8; i++) {
        const int stage = i & 1;
        if (i < 7) {
            load_stage(stage ^ 1, (i + 1) * 32);
            cp_commit();
            asm volatile("cp.async.wait_group 1;");
        } else {
            asm volatile("cp.async.wait_group 0;");
        }
        __syncthreads();

        const float* As_s = sm + stage * AS_STAGE;
        const float* Bs_s = sm + 2 * AS_STAGE + stage * BS_STAGE;

#pragma unroll
        for (int ks = 0; ks < 4; ks++) {
            const int kb = ks * 8;
            unsigned afrag[2][4];
#pragma unroll
            for (int ii = 0; ii < 2; ii++) {
                int r = wm * 32 + ii * 16;
                afrag[ii][0] = tf32_bits(As_s[(r + g    ) * AS_STRIDE + kb + c    ]);
                afrag[ii][1] = tf32_bits(As_s[(r + g + 8) * AS_STRIDE + kb + c    ]);
                afrag[ii][2] = tf32_bits(As_s[(r + g    ) * AS_STRIDE + kb + c + 4]);
                afrag[ii][3] = tf32_bits(As_s[(r + g + 8) * AS_STRIDE + kb + c + 4]);
            }
            const float4* b0p = (const float4*)(Bs_s + (kb + c    ) * BS_STRIDE
                                                + g * 16 + wn * 8);
            const float4* b1p = (const float4*)(Bs_s + (kb + c + 4) * BS_STRIDE
                                                + g * 16 + wn * 8);
            float4 b0a = b0p[0], b0b = b0p[1];
            float4 b1a = b1p[0], b1b = b1p[1];
            const float b0v[8] = {b0a.x, b0a.y, b0a.z, b0a.w,
                                  b0b.x, b0b.y, b0b.z, b0b.w};
            const float b1v[8] = {b1a.x, b1a.y, b1a.z, b1a.w,
                                  b1b.x, b1b.y, b1b.z, b1b.w};
#pragma unroll
            for (int j = 0; j < 8; j++) {
                unsigned b0 = __float_as_uint(b0v[j]);
                unsigned b1 = __float_as_uint(b1v[j]);
                mma_tf32(acc[0][j], afrag[0], b0, b1);
                mma_tf32(acc[1][j], afrag[1], b0, b1);
            }
        }
        __syncthreads();
    }

    // epilogue 1: store ft
#pragma unroll
    for (int i = 0; i < 2; i++) {
        int r0 = blockM + wm * 32 + i * 16 + g;
#pragma unroll
        for (int j = 0; j < 8; j++) {
            int cc = wn * 64 + j * 8 + c * 2;
            if (r0 < N_NODES)
                *(float2*)(C + (size_t)r0 * HD + cc) =
                    make_float2(acc[i][j][0], acc[i][j][1]);
            if (r0 + 8 < N_NODES)
                *(float2*)(C + (size_t)(r0 + 8) * HD + cc) =
                    make_float2(acc[i][j][2], acc[i][j][3]);
        }
    }

    // epilogue 2: el/er
    float elp[4][2], erp[4][2];
#pragma unroll
    for (int rs = 0; rs < 4; rs++)
#pragma unroll
        for (int hl = 0; hl < 2; hl++) { elp[rs][hl] = 0.f; erp[rs][hl] = 0.f; }
#pragma unroll
    for (int i = 0; i < 2; i++)
#pragma unroll
        for (int j = 0; j < 8; j++)
#pragma unroll
            for (int r = 0; r < 4; r++) {
                int col = wn * 64 + j * 8 + c * 2 + (r & 1);
                float wl = __ldg(attn_l + col);
                float wr = __ldg(attn_r + col);
                int rs = i * 2 + (r >> 1);
                elp[rs][j >> 2] += acc[i][j][r] * wl;
                erp[rs][j >> 2] += acc[i][j][r] * wr;
            }
#pragma unroll
    for (int rs = 0; rs < 4; rs++)
#pragma unroll
        for (int hl = 0; hl < 2; hl++) {
#pragma unroll
            for (int o = 1; o <= 2; o <<= 1) {
                elp[rs][hl] += __shfl_xor_sync(0xffffffffu, elp[rs][hl], o);
                erp[rs][hl] += __shfl_xor_sync(0xffffffffu, erp[rs][hl], o);
            }
        }
    if (c == 0) {
#pragma unroll
        for (int rs = 0; rs < 4; rs++) {
            int row = blockM + wm * 32 + (rs >> 1) * 16 + (rs & 1) * 8 + g;
            if (row < N_NODES) {
#pragma unroll
                for (int hl = 0; hl < 2; hl++) {
                    int h = wn * 2 + hl;
                    g_el[row * HEADS + h] = elp[rs][hl];
                    g_er[row * HEADS + h] = erp[rs][hl];
                }
            }
        }
    }
}

// ---------------- mega kernel: hist | gemm | scan | scatter ------------------
// blockIdx order == dependency order; consumers spin on producer flags.
__global__ __launch_bounds__(256, 2) void mega_kernel(
    const float* __restrict__ A, const float* __restrict__ attn_l,
    const float* __restrict__ attn_r, float* __restrict__ C,
    const int* __restrict__ src, const int* __restrict__ dst,
    const float* __restrict__ W)
{
    extern __shared__ float sm[];
    int bx = blockIdx.x;
    if (bx < HIST_BLOCKS) { hist_role(bx, dst, W); return; }
    bx -= HIST_BLOCKS;
    if (bx < GEMM_BLOCKS) { gemm_role(bx, A, attn_l, attn_r, C, sm); return; }
    bx -= GEMM_BLOCKS;
    if (bx < SCAN_BLOCKS) { scan_role(bx, (int*)sm); return; }
    bx -= SCAN_BLOCKS;
    scatter_role(bx, src, dst);
}

// ---- fused softmax + aggregation (unchanged from round 9) ------------------
__global__ __launch_bounds__(256) void agg_fused_kernel(
    float* __restrict__ rst, float* __restrict__ a_out, int has_a)
{
    __shared__ float ex_s[8][32][4];
    int warp = (blockIdx.x * blockDim.x + threadIdx.x) >> 5;
    int lane = threadIdx.x & 31;
    int wlocal = (threadIdx.x >> 5);
    if (warp >= N_NODES) return;
    const int h = lane >> 3;
    const int p0 = g_offsets[warp];
    const int p1 = g_offsets[warp + 1];
    const int deg = p1 - p0;
    const bool multi = deg > 32;

    if (deg == 0) {
        *(float4*)(rst + (size_t)warp * HD + lane * 4) =
            make_float4(0.f, 0.f, 0.f, 0.f);
        return;
    }

    float4 er4 = *(const float4*)(g_er + (size_t)warp * HEADS);
    float4 acc = make_float4(0.f, 0.f, 0.f, 0.f);
    float denh = 0.0f;
    const float4* ft4l = (const float4*)g_ft + lane;

    float4 ex4 = make_float4(0.f, 0.f, 0.f, 0.f);
    int eid = 0;

    for (int base = p0; base < p1; base += 32) {
        int p = base + lane;
        ex4 = make_float4(0.f, 0.f, 0.f, 0.f);
        int s = 0;
        if (p < p1) {
            unsigned long long pk = g_csr[p];
            s = (int)(pk >> 32);
            eid = (int)(unsigned)(pk & 0xffffffffULL);
            float4 el4 = *(const float4*)(g_el + (size_t)s * HEADS);
            float4 v;
            v.x = el4.x + er4.x; v.y = el4.y + er4.y;
            v.z = el4.z + er4.z; v.w = el4.w + er4.w;
            v.x = v.x > 0.f ? v.x : NEG_SLOPE * v.x;
            v.y = v.y > 0.f ? v.y : NEG_SLOPE * v.y;
            v.z = v.z > 0.f ? v.z : NEG_SLOPE * v.z;
            v.w = v.w > 0.f ? v.w : NEG_SLOPE * v.w;
            ex4.x = __expf(v.x); ex4.y = __expf(v.y);
            ex4.z = __expf(v.z); ex4.w = __expf(v.w);
            if (has_a && multi) *(float4*)(g_e + (size_t)p * HEADS) = ex4;
        }

        __syncwarp();
        *(float4*)&ex_s[wlocal][lane][0] = ex4;
        __syncwarp();

        int cnt = min(p1 - base, 32);
        for (int q0 = 0; q0 < cnt; q0 += 4) {
            int m = cnt - q0;
            float4 f0, f1, f2, f3;
            int sq;
            sq = __shfl_sync(0xffffffffu, s, q0);
            f0 = ft4l[(unsigned)sq * 32u];
            if (m > 1) { sq = __shfl_sync(0xffffffffu, s, q0 + 1);
                         f1 = ft4l[(unsigned)sq * 32u]; }
            if (m > 2) { sq = __shfl_sync(0xffffffffu, s, q0 + 2);
                         f2 = ft4l[(unsigned)sq * 32u]; }
            if (m > 3) { sq = __shfl_sync(0xffffffffu, s, q0 + 3);
                         f3 = ft4l[(unsigned)sq * 32u]; }
            float e0 = ex_s[wlocal][q0][h];
            denh += e0;
            acc.x += e0 * f0.x; acc.y += e0 * f0.y;
            acc.z += e0 * f0.z; acc.w += e0 * f0.w;
            if (m > 1) {
                float e1 = ex_s[wlocal][q0 + 1][h];
                denh += e1;
                acc.x += e1 * f1.x; acc.y += e1 * f1.y;
                acc.z += e1 * f1.z; acc.w += e1 * f1.w;
            }
            if (m > 2) {
                float e2 = ex_s[wlocal][q0 + 2][h];
                denh += e2;
                acc.x += e2 * f2.x; acc.y += e2 * f2.y;
                acc.z += e2 * f2.z; acc.w += e2 * f2.w;
            }
            if (m > 3) {
                float e3 = ex_s[wlocal][q0 + 3][h];
                denh += e3;
                acc.x += e3 * f3.x; acc.y += e3 * f3.y;
                acc.z += e3 * f3.z; acc.w += e3 * f3.w;
            }
        }
    }

    float rdh = 1.0f / denh;
    acc.x *= rdh; acc.y *= rdh; acc.z *= rdh; acc.w *= rdh;
    *(float4*)(rst + (size_t)warp * HD + lane * 4) = acc;

    if (has_a) {
        float4 rd4;
        rd4.x = __shfl_sync(0xffffffffu, rdh, 0);
        rd4.y = __shfl_sync(0xffffffffu, rdh, 8);
        rd4.z = __shfl_sync(0xffffffffu, rdh, 16);
        rd4.w = __shfl_sync(0xffffffffu, rdh, 24);
        if (!multi) {
            int p = p0 + lane;
            if (p < p1) {
                float4 a4 = make_float4(ex4.x * rd4.x, ex4.y * rd4.y,
                                        ex4.z * rd4.z, ex4.w * rd4.w);
                *(float4*)(a_out + (size_t)eid * HEADS) = a4;
            }
        } else {
            for (int p = p0 + lane; p < p1; p += 32) {
                float4 e4 = *(const float4*)(g_e + (size_t)p * HEADS);
                int e = (int)(unsigned)(g_csr[p] & 0xffffffffULL);
                float4 a4 = make_float4(e4.x * rd4.x, e4.y * rd4.y,
                                        e4.z * rd4.z, e4.w * rd4.w);
                *(float4*)(a_out + (size_t)e * HEADS) = a4;
            }
        }
    }
}

// ---------------- launch ------------------------------------------------------
extern "C" void kernel_launch(void* const* d_in, const int* in_sizes, int n_in,
                              void* d_out, int out_size)
{
    const float* feat   = (const float*)d_in[0];
    const float* W      = (const float*)d_in[1];
    const float* attn_l = (const float*)d_in[2];
    const float* attn_r = (const float*)d_in[3];
    const int*   src    = (const int*)d_in[4];
    const int*   dst    = (const int*)d_in[5];
    float* out = (float*)d_out;

    const int rst_elems = N_NODES * HD;
    const int has_a = (out_size >= rst_elems + N_EDGES * HEADS) ? 1 : 0;
    float* a_out = out + rst_elems;

    float* ft_dev;   cudaGetSymbolAddress((void**)&ft_dev, g_ft);
    int*   pool_dev; cudaGetSymbolAddress((void**)&pool_dev, g_pool);

    cudaFuncSetAttribute(mega_kernel,
                         cudaFuncAttributeMaxDynamicSharedMemorySize,
                         GEMM_SMEM_BYTES);

    // zero counts + scan states + flags in one shot
    cudaMemsetAsync(pool_dev, 0, (N_NODES + 260) * sizeof(int));

    const int total_blocks = HIST_BLOCKS + GEMM_BLOCKS + SCAN_BLOCKS + SCAT_BLOCKS;
    mega_kernel<<<total_blocks, 256, GEMM_SMEM_BYTES>>>(
        feat, attn_l, attn_r, ft_dev, src, dst, W);

    agg_fused_kernel<<<(N_NODES * 32 + 255) / 256, 256>>>(out, a_out, has_a);
}

// round 11
// speedup vs baseline: 1.0604x; 1.0604x over previous
#include <cuda_runtime.h>
#include <cuda_bf16.h>
#include <math.h>

#define N_NODES 100000
#define N_EDGES 640000
#define IN_FEATS 256
#define HEADS 4
#define OUT_FEATS 32
#define HD (HEADS * OUT_FEATS)   // 128
#define NEG_SLOPE 0.2f

#define GEMM_BLOCKS ((N_NODES + 127) / 128)      // 782
#define SCAN_BLOCKS 98                           // ceil(100000/1024)

// GEMM smem geometry (floats)
#define AS_STRIDE 36
#define BS_STRIDE 132
#define AS_STAGE (128 * AS_STRIDE)
#define BS_STAGE (32 * BS_STRIDE)
#define GEMM_SMEM_BYTES ((2 * AS_STAGE + 2 * BS_STAGE) * 4)   // 70656 B

// ---------------- scratch (no allocs allowed) ----------------
__device__ float    g_ft[(size_t)N_NODES * HD];
__device__ float    g_el[N_NODES * HEADS];
__device__ float    g_er[N_NODES * HEADS];
__device__ float    g_e [(size_t)N_EDGES * HEADS];   // exp(logit), CSR order
__device__ float    g_wt[IN_FEATS * HD];             // tf32-rounded, permuted W
__device__ int      g_pool[N_NODES + 256];           // counts + scan states
__device__ int      g_offsets[N_NODES + 1];
__device__ int      g_cursor[N_NODES];
__device__ unsigned long long g_csr[N_EDGES];        // (src<<32)|edge_id

#define G_COUNTS (g_pool)
#define G_STATE  ((unsigned long long*)(g_pool + N_NODES))

// ---------------- helpers ----------------
__device__ __forceinline__ unsigned tf32_bits(float x) {
    unsigned u;
    asm("cvt.rna.tf32.f32 %0, %1;" : "=r"(u) : "f"(x));
    return u;
}
__device__ __forceinline__ float to_tf32(float x) {
    return __uint_as_float(tf32_bits(x));
}
__device__ __forceinline__ void cp_async16(unsigned smem, const void* gmem,
                                           int src_bytes) {
    asm volatile("cp.async.cg.shared.global [%0], [%1], 16, %2;"
                 :: "r"(smem), "l"(gmem), "r"(src_bytes));
}
__device__ __forceinline__ void cp_commit() {
    asm volatile("cp.async.commit_group;");
}
__device__ __forceinline__ void mma_tf32(float* d, const unsigned* a,
                                         unsigned b0, unsigned b1) {
    asm volatile(
        "mma.sync.aligned.m16n8k8.row.col.f32.tf32.tf32.f32 "
        "{%0,%1,%2,%3}, {%4,%5,%6,%7}, {%8,%9}, {%0,%1,%2,%3};"
        : "+f"(d[0]), "+f"(d[1]), "+f"(d[2]), "+f"(d[3])
        : "r"(a[0]), "r"(a[1]), "r"(a[2]), "r"(a[3]), "r"(b0), "r"(b1));
}

// ---------------- scan body (256 threads, 1024 items/block) ------------------
__device__ void scan_body(int b, int* smi) {
    const int t = threadIdx.x;
    const int lane = t & 31, w = t >> 5;
    const int base = b * 1024 + t * 4;

    int v0 = 0, v1 = 0, v2 = 0, v3 = 0;
    if (base + 3 < N_NODES) {
        int4 q = *(const int4*)(G_COUNTS + base);
        v0 = q.x; v1 = q.y; v2 = q.z; v3 = q.w;
    } else {
        if (base + 0 < N_NODES) v0 = G_COUNTS[base + 0];
        if (base + 1 < N_NODES) v1 = G_COUNTS[base + 1];
        if (base + 2 < N_NODES) v2 = G_COUNTS[base + 2];
        if (base + 3 < N_NODES) v3 = G_COUNTS[base + 3];
    }
    int tsum = v0 + v1 + v2 + v3;
    int x = tsum;
#pragma unroll
    for (int o = 1; o < 32; o <<= 1) {
        int u = __shfl_up_sync(0xffffffffu, x, o);
        if (lane >= o) x += u;
    }
    if (lane == 31) smi[w] = x;
    __syncthreads();
    if (t < 8) {
        int acc = 0;
        for (int j = 0; j <= t; j++) acc += smi[j];
        smi[t + 16] = acc;
    }
    __syncthreads();
    int warp_off = (w > 0) ? smi[16 + w - 1] : 0;
    int total = smi[16 + 7];

    if (t == 0) {
        unsigned long long* st = G_STATE;
        int excl = 0;
        if (b == 0) {
            __threadfence();
            atomicExch(&st[0], (2ULL << 32) | (unsigned)total);
        } else {
            __threadfence();
            atomicExch(&st[b], (1ULL << 32) | (unsigned)total);
            for (int j = b - 1; j >= 0;) {
                unsigned long long sv;
                do { sv = atomicAdd(&st[j], 0ULL); } while ((sv >> 32) == 0ULL);
                excl += (int)(sv & 0xffffffffULL);
                if ((sv >> 32) == 2ULL) break;
                j--;
            }
            __threadfence();
            atomicExch(&st[b], (2ULL << 32) | (unsigned)(excl + total));
        }
        smi[8] = excl;
    }
    __syncthreads();
    int pre = smi[8] + warp_off + (x - tsum);

    int o0 = pre, o1 = pre + v0, o2 = pre + v0 + v1, o3 = pre + v0 + v1 + v2;
    if (base + 3 < N_NODES) {
        *(int4*)(g_offsets + base) = make_int4(o0, o1, o2, o3);
        *(int4*)(g_cursor  + base) = make_int4(o0, o1, o2, o3);
    } else {
        if (base + 0 < N_NODES) { g_offsets[base+0] = o0; g_cursor[base+0] = o0; }
        if (base + 1 < N_NODES) { g_offsets[base+1] = o1; g_cursor[base+1] = o1; }
        if (base + 2 < N_NODES) { g_offsets[base+2] = o2; g_cursor[base+2] = o2; }
        if (base + 3 < N_NODES) { g_offsets[base+3] = o3; g_cursor[base+3] = o3; }
    }
    if (b == 0 && t == 0) g_offsets[N_NODES] = N_EDGES;
}

// ---- GEMM (TF32 MMA, cp.async 2-stage) + el/er epilogue + scan blocks ------
__global__ __launch_bounds__(256, 2) void gemm_tf32_kernel(
    const float* __restrict__ A, const float* __restrict__ B,
    const float* __restrict__ attn_l, const float* __restrict__ attn_r,
    float* __restrict__ C)
{
    extern __shared__ float sm[];
    if (blockIdx.x >= GEMM_BLOCKS) {
        scan_body(blockIdx.x - GEMM_BLOCKS, (int*)sm);
        return;
    }
    const unsigned sm_u32 = (unsigned)__cvta_generic_to_shared(sm);
    const int tid  = threadIdx.x;
    const int warp = tid >> 5, lane = tid & 31;
    const int wm = warp >> 1, wn = warp & 1;
    const int g = lane >> 2, c = lane & 3;
    const int blockM = blockIdx.x * 128;

    float acc[2][8][4];
#pragma unroll
    for (int i = 0; i < 2; i++)
#pragma unroll
        for (int j = 0; j < 8; j++)
#pragma unroll
            for (int r = 0; r < 4; r++) acc[i][j][r] = 0.0f;

    auto load_stage = [&](int stage, int k0) {
        unsigned as_base = sm_u32 + (unsigned)(stage * AS_STAGE) * 4u;
        unsigned bs_base = sm_u32 + (unsigned)((2 * AS_STAGE) + stage * BS_STAGE) * 4u;
#pragma unroll
        for (int it = 0; it < 4; it++) {
            int f   = tid + it * 256;
            int row = f >> 3;
            int seg = f & 7;
            int grow = blockM + row;
            int sz = (grow < N_NODES) ? 16 : 0;
            cp_async16(as_base + (unsigned)(row * AS_STRIDE + seg * 4) * 4u,
                       A + (size_t)grow * IN_FEATS + k0 + seg * 4, sz);
        }
#pragma unroll
        for (int it = 0; it < 4; it++) {
            int f  = tid + it * 256;
            int kr = f >> 5;
            int cs = (f & 31) * 4;
            cp_async16(bs_base + (unsigned)(kr * BS_STRIDE + cs) * 4u,
                       B + (size_t)(k0 + kr) * HD + cs, 16);
        }
    };

    load_stage(0, 0);
    cp_commit();

    for (int i = 0; i < 8; i++) {
        const int stage = i & 1;
        if (i < 7) {
            load_stage(stage ^ 1, (i + 1) * 32);
            cp_commit();
            asm volatile("cp.async.wait_group 1;");
        } else {
            asm volatile("cp.async.wait_group 0;");
        }
        __syncthreads();

        const float* As_s = sm + stage * AS_STAGE;
        const float* Bs_s = sm + 2 * AS_STAGE + stage * BS_STAGE;

#pragma unroll
        for (int ks = 0; ks < 4; ks++) {
            const int kb = ks * 8;
            unsigned afrag[2][4];
#pragma unroll
            for (int ii = 0; ii < 2; ii++) {
                int r = wm * 32 + ii * 16;
                afrag[ii][0] = tf32_bits(As_s[(r + g    ) * AS_STRIDE + kb + c    ]);
                afrag[ii][1] = tf32_bits(As_s[(r + g + 8) * AS_STRIDE + kb + c    ]);
                afrag[ii][2] = tf32_bits(As_s[(r + g    ) * AS_STRIDE + kb + c + 4]);
                afrag[ii][3] = tf32_bits(As_s[(r + g + 8) * AS_STRIDE + kb + c + 4]);
            }
            const float4* b0p = (const float4*)(Bs_s + (kb + c    ) * BS_STRIDE
                                                + g * 16 + wn * 8);
            const float4* b1p = (const float4*)(Bs_s + (kb + c + 4) * BS_STRIDE
                                                + g * 16 + wn * 8);
            float4 b0a = b0p[0], b0b = b0p[1];
            float4 b1a = b1p[0], b1b = b1p[1];
            const float b0v[8] = {b0a.x, b0a.y, b0a.z, b0a.w,
                                  b0b.x, b0b.y, b0b.z, b0b.w};
            const float b1v[8] = {b1a.x, b1a.y, b1a.z, b1a.w,
                                  b1b.x, b1b.y, b1b.z, b1b.w};
#pragma unroll
            for (int j = 0; j < 8; j++) {
                unsigned b0 = __float_as_uint(b0v[j]);
                unsigned b1 = __float_as_uint(b1v[j]);
                mma_tf32(acc[0][j], afrag[0], b0, b1);
                mma_tf32(acc[1][j], afrag[1], b0, b1);
            }
        }
        __syncthreads();
    }

    // epilogue 1: store ft
#pragma unroll
    for (int i = 0; i < 2; i++) {
        int r0 = blockM + wm * 32 + i * 16 + g;
#pragma unroll
        for (int j = 0; j < 8; j++) {
            int cc = wn * 64 + j * 8 + c * 2;
            if (r0 < N_NODES)
                *(float2*)(C + (size_t)r0 * HD + cc) =
                    make_float2(acc[i][j][0], acc[i][j][1]);
            if (r0 + 8 < N_NODES)
                *(float2*)(C + (size_t)(r0 + 8) * HD + cc) =
                    make_float2(acc[i][j][2], acc[i][j][3]);
        }
    }

    // epilogue 2: el/er
    float elp[4][2], erp[4][2];
#pragma unroll
    for (int rs = 0; rs < 4; rs++)
#pragma unroll
        for (int hl = 0; hl < 2; hl++) { elp[rs][hl] = 0.f; erp[rs][hl] = 0.f; }
#pragma unroll
    for (int i = 0; i < 2; i++)
#pragma unroll
        for (int j = 0; j < 8; j++)
#pragma unroll
            for (int r = 0; r < 4; r++) {
                int col = wn * 64 + j * 8 + c * 2 + (r & 1);
                float wl = __ldg(attn_l + col);
                float wr = __ldg(attn_r + col);
                int rs = i * 2 + (r >> 1);
                elp[rs][j >> 2] += acc[i][j][r] * wl;
                erp[rs][j >> 2] += acc[i][j][r] * wr;
            }
#pragma unroll
    for (int rs = 0; rs < 4; rs++)
#pragma unroll
        for (int hl = 0; hl < 2; hl++) {
#pragma unroll
            for (int o = 1; o <= 2; o <<= 1) {
                elp[rs][hl] += __shfl_xor_sync(0xffffffffu, elp[rs][hl], o);
                erp[rs][hl] += __shfl_xor_sync(0xffffffffu, erp[rs][hl], o);
            }
        }
    if (c == 0) {
#pragma unroll
        for (int rs = 0; rs < 4; rs++) {
            int row = blockM + wm * 32 + (rs >> 1) * 16 + (rs & 1) * 8 + g;
            if (row < N_NODES) {
#pragma unroll
                for (int hl = 0; hl < 2; hl++) {
                    int h = wn * 2 + hl;
                    g_el[row * HEADS + h] = elp[rs][hl];
                    g_er[row * HEADS + h] = erp[rs][hl];
                }
            }
        }
    }
}

// -------- histogram (int4) + fused tf32 round + PERMUTE of W ----------------
__global__ void hist_kernel(const int* __restrict__ dst,
                            const float* __restrict__ W) {
    int i = blockIdx.x * blockDim.x + threadIdx.x;
    if (i < (IN_FEATS * HD) / 4) {
        float4 v = ((const float4*)W)[i];
        int k = (i * 4) / HD;
        int n = (i * 4) % HD;
        float vv[4] = {to_tf32(v.x), to_tf32(v.y), to_tf32(v.z), to_tf32(v.w)};
#pragma unroll
        for (int q = 0; q < 4; q++) {
            int nn = n + q;
            int p = (nn & 7) * 16 + ((nn >> 6) & 1) * 8 + ((nn >> 3) & 7);
            g_wt[k * HD + p] = vv[q];
        }
    }
    if (i >= N_EDGES / 4) return;
    int4 d = ((const int4*)dst)[i];
    atomicAdd(&G_COUNTS[d.x], 1);
    atomicAdd(&G_COUNTS[d.y], 1);
    atomicAdd(&G_COUNTS[d.z], 1);
    atomicAdd(&G_COUNTS[d.w], 1);
}

// ---- CSR scatter + softmax numerator: runs AFTER gemm (el/er ready) --------
// Stores packed (src, edge_id) and the per-edge exp vector in CSR order, so
// the agg kernel never touches el/er or __expf.
__global__ void scatter_kernel(const int* __restrict__ src,
                               const int* __restrict__ dst) {
    int e = blockIdx.x * blockDim.x + threadIdx.x;
    if (e >= N_EDGES) return;
    int s = src[e], d = dst[e];
    float4 el4 = *(const float4*)(g_el + (size_t)s * HEADS);
    float4 er4 = *(const float4*)(g_er + (size_t)d * HEADS);
    float4 v;
    v.x = el4.x + er4.x; v.y = el4.y + er4.y;
    v.z = el4.z + er4.z; v.w = el4.w + er4.w;
    v.x = v.x > 0.f ? v.x : NEG_SLOPE * v.x;
    v.y = v.y > 0.f ? v.y : NEG_SLOPE * v.y;
    v.z = v.z > 0.f ? v.z : NEG_SLOPE * v.z;
    v.w = v.w > 0.f ? v.w : NEG_SLOPE * v.w;
    float4 ex4;
    ex4.x = __expf(v.x); ex4.y = __expf(v.y);
    ex4.z = __expf(v.z); ex4.w = __expf(v.w);
    int pos = atomicAdd(&g_cursor[d], 1);
    g_csr[pos] = ((unsigned long long)(unsigned)s << 32) | (unsigned)e;
    *(float4*)(g_e + (size_t)pos * HEADS) = ex4;
}

// ---- aggregation: one warp per dst node, zero atomics, no exp/el access ----
__global__ __launch_bounds__(256, 6) void agg_fused_kernel(
    float* __restrict__ rst, float* __restrict__ a_out, int has_a)
{
    __shared__ float ex_s[8][32][4];   // [warp][edge-in-chunk][head]
    int warp = (blockIdx.x * blockDim.x + threadIdx.x) >> 5;
    int lane = threadIdx.x & 31;
    int wlocal = (threadIdx.x >> 5);
    if (warp >= N_NODES) return;
    const int h = lane >> 3;
    const int p0 = g_offsets[warp];
    const int p1 = g_offsets[warp + 1];
    const int deg = p1 - p0;

    if (deg == 0) {
        *(float4*)(rst + (size_t)warp * HD + lane * 4) =
            make_float4(0.f, 0.f, 0.f, 0.f);
        return;
    }

    float4 acc = make_float4(0.f, 0.f, 0.f, 0.f);
    float denh = 0.0f;
    const float4* ft4l = (const float4*)g_ft + lane;

    float4 ex4 = make_float4(0.f, 0.f, 0.f, 0.f);   // last chunk, my edge
    int eid = 0;

    for (int base = p0; base < p1; base += 32) {
        int p = base + lane;
        ex4 = make_float4(0.f, 0.f, 0.f, 0.f);
        int s = 0;
        if (p < p1) {
            unsigned long long pk = g_csr[p];
            s = (int)(pk >> 32);
            eid = (int)(unsigned)(pk & 0xffffffffULL);
            ex4 = *(const float4*)(g_e + (size_t)p * HEADS);   // coalesced
        }

        __syncwarp();
        *(float4*)&ex_s[wlocal][lane][0] = ex4;
        __syncwarp();

        int cnt = min(p1 - base, 32);
        for (int q0 = 0; q0 < cnt; q0 += 4) {
            int m = cnt - q0;
            float4 f0, f1, f2, f3;
            int sq;
            sq = __shfl_sync(0xffffffffu, s, q0);
            f0 = ft4l[(unsigned)sq * 32u];
            if (m > 1) { sq = __shfl_sync(0xffffffffu, s, q0 + 1);
                         f1 = ft4l[(unsigned)sq * 32u]; }
            if (m > 2) { sq = __shfl_sync(0xffffffffu, s, q0 + 2);
                         f2 = ft4l[(unsigned)sq * 32u]; }
            if (m > 3) { sq = __shfl_sync(0xffffffffu, s, q0 + 3);
                         f3 = ft4l[(unsigned)sq * 32u]; }
            float e0 = ex_s[wlocal][q0][h];
            denh += e0;
            acc.x += e0 * f0.x; acc.y += e0 * f0.y;
            acc.z += e0 * f0.z; acc.w += e0 * f0.w;
            if (m > 1) {
                float e1 = ex_s[wlocal][q0 + 1][h];
                denh += e1;
                acc.x += e1 * f1.x; acc.y += e1 * f1.y;
                acc.z += e1 * f1.z; acc.w += e1 * f1.w;
            }
            if (m > 2) {
                float e2 = ex_s[wlocal][q0 + 2][h];
                denh += e2;
                acc.x += e2 * f2.x; acc.y += e2 * f2.y;
                acc.z += e2 * f2.z; acc.w += e2 * f2.w;
            }
            if (m > 3) {
                float e3 = ex_s[wlocal][q0 + 3][h];
                denh += e3;
                acc.x += e3 * f3.x; acc.y += e3 * f3.y;
                acc.z += e3 * f3.z; acc.w += e3 * f3.w;
            }
        }
    }

    float rdh = 1.0f / denh;
    acc.x *= rdh; acc.y *= rdh; acc.z *= rdh; acc.w *= rdh;
    *(float4*)(rst + (size_t)warp * HD + lane * 4) = acc;

    if (has_a) {
        float4 rd4;
        rd4.x = __shfl_sync(0xffffffffu, rdh, 0);
        rd4.y = __shfl_sync(0xffffffffu, rdh, 8);
        rd4.z = __shfl_sync(0xffffffffu, rdh, 16);
        rd4.w = __shfl_sync(0xffffffffu, rdh, 24);
        if (deg <= 32) {
            int p = p0 + lane;
            if (p < p1) {
                float4 a4 = make_float4(ex4.x * rd4.x, ex4.y * rd4.y,
                                        ex4.z * rd4.z, ex4.w * rd4.w);
                *(float4*)(a_out + (size_t)eid * HEADS) = a4;
            }
        } else {
            for (int p = p0 + lane; p < p1; p += 32) {
                float4 e4 = *(const float4*)(g_e + (size_t)p * HEADS);
                int e = (int)(unsigned)(g_csr[p] & 0xffffffffULL);
                float4 a4 = make_float4(e4.x * rd4.x, e4.y * rd4.y,
                                        e4.z * rd4.z, e4.w * rd4.w);
                *(float4*)(a_out + (size_t)e * HEADS) = a4;
            }
        }
    }
}

// ---------------- launch ------------------------------------------------------
extern "C" void kernel_launch(void* const* d_in, const int* in_sizes, int n_in,
                              void* d_out, int out_size)
{
    const float* feat   = (const float*)d_in[0];
    const float* W      = (const float*)d_in[1];
    const float* attn_l = (const float*)d_in[2];
    const float* attn_r = (const float*)d_in[3];
    const int*   src    = (const int*)d_in[4];
    const int*   dst    = (const int*)d_in[5];
    float* out = (float*)d_out;

    const int rst_elems = N_NODES * HD;
    const int has_a = (out_size >= rst_elems + N_EDGES * HEADS) ? 1 : 0;
    float* a_out = out + rst_elems;

    float* ft_dev;   cudaGetSymbolAddress((void**)&ft_dev, g_ft);
    float* wt_dev;   cudaGetSymbolAddress((void**)&wt_dev, g_wt);
    int*   pool_dev; cudaGetSymbolAddress((void**)&pool_dev, g_pool);

    cudaFuncSetAttribute(gemm_tf32_kernel,
                         cudaFuncAttributeMaxDynamicSharedMemorySize,
                         GEMM_SMEM_BYTES);

    cudaMemsetAsync(pool_dev, 0, (N_NODES + 256) * sizeof(int));

    hist_kernel<<<(N_EDGES / 4 + 255) / 256, 256>>>(dst, W);

    gemm_tf32_kernel<<<GEMM_BLOCKS + SCAN_BLOCKS, 256, GEMM_SMEM_BYTES>>>(
        feat, wt_dev, attn_l, attn_r, ft_dev);

    scatter_kernel<<<(N_EDGES + 255) / 256, 256>>>(src, dst);

    agg_fused_kernel<<<(N_NODES * 32 + 255) / 256, 256>>>(out, a_out, has_a);
}